// round 1
// baseline (speedup 1.0000x reference)
#include <cuda_runtime.h>
#include <cuda_bf16.h>
#include <math.h>

// Problem constants (fixed by setup_inputs)
#define B_SZ 64
#define D_SZ 2048
#define H_SZ 256
#define DT    32          // d-tiles of 64 rows: D_SZ / 64
#define NCHUNK 8          // d-chunks for weighted sum: D_SZ / 256

// Scratch (allocation-free rule: __device__ globals)
__device__ float g_scores [B_SZ * D_SZ];          // scores, then softmax weights (in-place)
__device__ float g_bias   [B_SZ * H_SZ];          // c[b][h] = W2@ctx + b2 + W3@hid
__device__ float g_partial[B_SZ * NCHUNK * H_SZ]; // partial weighted sums

// ---------------------------------------------------------------------------
// Kernel 1: per-batch bias vector c[b][h] = sum_k ctx[b,k]W2[h,k] + b2[h]
//                                         + sum_k hid[b,k]W3[h,k]
// grid = B_SZ, block = H_SZ
// ---------------------------------------------------------------------------
__global__ void bias_kernel(const float* __restrict__ ctx,
                            const float* __restrict__ hid,
                            const float* __restrict__ W2,
                            const float* __restrict__ b2,
                            const float* __restrict__ W3) {
    int b = blockIdx.x;
    int h = threadIdx.x;
    __shared__ float cs[H_SZ];
    __shared__ float hs[H_SZ];
    cs[h] = ctx[b * H_SZ + h];
    hs[h] = hid[b * H_SZ + h];
    __syncthreads();

    const float4* w2r = reinterpret_cast<const float4*>(W2 + (size_t)h * H_SZ);
    const float4* w3r = reinterpret_cast<const float4*>(W3 + (size_t)h * H_SZ);
    float acc = b2[h];
    #pragma unroll 8
    for (int k4 = 0; k4 < H_SZ / 4; k4++) {
        float4 w2v = w2r[k4];
        float4 w3v = w3r[k4];
        int k = k4 * 4;
        acc += cs[k + 0] * w2v.x + cs[k + 1] * w2v.y + cs[k + 2] * w2v.z + cs[k + 3] * w2v.w;
        acc += hs[k + 0] * w3v.x + hs[k + 1] * w3v.y + hs[k + 2] * w3v.z + hs[k + 3] * w3v.w;
    }
    g_bias[b * H_SZ + h] = acc;
}

// ---------------------------------------------------------------------------
// Kernel 2: fused GEMM + tanh + W4-dot -> scores.
// CTA tile: 64 question rows (M) x 256 hidden units (N), K = 256.
// Thread microtile: 4 (M) x 16 (N); threads laid out 16 (ty, M) x 16 (tx, N).
// A (q tile, 64x256, row-padded to 260) resident in SMEM; W1^T in 64-wide
// k-slices. Epilogue: score_row = sum_h tanh(v[h]+c[h])*W4[h] via half-warp
// shuffle reduce. g1 is never materialized in GMEM.
// grid = (DT, B_SZ), block = 256, dyn smem = (64*260 + 64*256)*4 bytes
// ---------------------------------------------------------------------------
#define A_STRIDE 260
#define SMEM_BYTES ((64 * A_STRIDE + 64 * H_SZ) * 4)

__global__ void __launch_bounds__(256, 1)
gemm_score_kernel(const float* __restrict__ Q,
                  const float* __restrict__ W1,
                  const float* __restrict__ W4,
                  const float* __restrict__ b4) {
    extern __shared__ float sm[];
    float* As = sm;                    // [64][A_STRIDE]
    float* Bs = sm + 64 * A_STRIDE;    // [64][H_SZ]  (Bs[kk][h] = W1[h][k0+kk])
    __shared__ float cs[H_SZ];
    __shared__ float w4s[H_SZ];

    int b   = blockIdx.y;
    int dt  = blockIdx.x;
    int tid = threadIdx.x;
    int tx  = tid & 15;    // N direction
    int ty  = tid >> 4;    // M direction

    cs[tid]  = g_bias[b * H_SZ + tid];
    w4s[tid] = W4[tid];

    // Load A: 64 rows x 256 cols = 4096 float4, 16 per thread. Coalesced.
    const float4* qg = reinterpret_cast<const float4*>(
        Q + ((size_t)b * D_SZ + (size_t)dt * 64) * H_SZ);
    #pragma unroll
    for (int r = 0; r < 16; r++) {
        int idx = r * 256 + tid;     // float4 index in 64x64-float4 tile
        int row = idx >> 6;
        int c4  = idx & 63;
        float4 v = qg[idx];
        *reinterpret_cast<float4*>(As + row * A_STRIDE + c4 * 4) = v;
    }

    float acc[4][16];
    #pragma unroll
    for (int i = 0; i < 4; i++)
        #pragma unroll
        for (int j = 0; j < 16; j++) acc[i][j] = 0.0f;

    const float* Ab = As + (ty * 4) * A_STRIDE;

    for (int kb = 0; kb < 4; kb++) {
        __syncthreads();
        // Load + transpose W1 k-slice: thread owns output row h = tid,
        // reads 64 contiguous floats of W1[h], scatters into Bs columns.
        const float4* w1r = reinterpret_cast<const float4*>(
            W1 + (size_t)tid * H_SZ + kb * 64);
        #pragma unroll
        for (int q4 = 0; q4 < 16; q4++) {
            float4 v = w1r[q4];
            Bs[(q4 * 4 + 0) * H_SZ + tid] = v.x;
            Bs[(q4 * 4 + 1) * H_SZ + tid] = v.y;
            Bs[(q4 * 4 + 2) * H_SZ + tid] = v.z;
            Bs[(q4 * 4 + 3) * H_SZ + tid] = v.w;
        }
        __syncthreads();

        #pragma unroll 4
        for (int kk = 0; kk < 64; kk++) {
            int k = kb * 64 + kk;
            float av[4];
            #pragma unroll
            for (int i = 0; i < 4; i++) av[i] = Ab[i * A_STRIDE + k];

            const float4* Bk = reinterpret_cast<const float4*>(Bs + kk * H_SZ + tx * 16);
            float bv[16];
            #pragma unroll
            for (int j4 = 0; j4 < 4; j4++) {
                float4 v = Bk[j4];
                bv[j4 * 4 + 0] = v.x; bv[j4 * 4 + 1] = v.y;
                bv[j4 * 4 + 2] = v.z; bv[j4 * 4 + 3] = v.w;
            }
            #pragma unroll
            for (int i = 0; i < 4; i++)
                #pragma unroll
                for (int j = 0; j < 16; j++)
                    acc[i][j] = fmaf(av[i], bv[j], acc[i][j]);
        }
    }

    // Fused epilogue: score = sum_h tanh(v+c)*W4 + b4, reduced over tx (16 lanes)
    float b4v = b4[0];
    #pragma unroll
    for (int i = 0; i < 4; i++) {
        float part = 0.0f;
        #pragma unroll
        for (int j = 0; j < 16; j++) {
            int h = tx * 16 + j;
            part += tanhf(acc[i][j] + cs[h]) * w4s[h];
        }
        #pragma unroll
        for (int off = 8; off > 0; off >>= 1)
            part += __shfl_down_sync(0xffffffffu, part, off, 16);
        if (tx == 0)
            g_scores[b * D_SZ + dt * 64 + ty * 4 + i] = part + b4v;
    }
}

// ---------------------------------------------------------------------------
// Kernel 3: softmax over D per batch. grid = B_SZ, block = 256.
// ---------------------------------------------------------------------------
__global__ void softmax_kernel() {
    int b   = blockIdx.x;
    int tid = threadIdx.x;
    __shared__ float red[256];

    float v[NCHUNK];
    float m = -1e30f;
    #pragma unroll
    for (int i = 0; i < NCHUNK; i++) {
        v[i] = g_scores[b * D_SZ + i * 256 + tid];
        m = fmaxf(m, v[i]);
    }
    red[tid] = m;
    __syncthreads();
    for (int s = 128; s > 0; s >>= 1) {
        if (tid < s) red[tid] = fmaxf(red[tid], red[tid + s]);
        __syncthreads();
    }
    m = red[0];
    __syncthreads();

    float ssum = 0.0f;
    #pragma unroll
    for (int i = 0; i < NCHUNK; i++) {
        v[i] = expf(v[i] - m);
        ssum += v[i];
    }
    red[tid] = ssum;
    __syncthreads();
    for (int s = 128; s > 0; s >>= 1) {
        if (tid < s) red[tid] += red[tid + s];
        __syncthreads();
    }
    float inv = 1.0f / red[0];

    #pragma unroll
    for (int i = 0; i < NCHUNK; i++)
        g_scores[b * D_SZ + i * 256 + tid] = v[i] * inv;
}

// ---------------------------------------------------------------------------
// Kernel 4: partial weighted sums (deterministic, no atomics).
// CTA = (chunk c of 256 d-rows, batch b); thread t owns hidden index t.
// grid = (NCHUNK, B_SZ), block = 256.
// ---------------------------------------------------------------------------
__global__ void __launch_bounds__(256)
wsum_kernel(const float* __restrict__ Q) {
    int b = blockIdx.y;
    int c = blockIdx.x;
    int t = threadIdx.x;
    __shared__ float ws[256];
    ws[t] = g_scores[b * D_SZ + c * 256 + t];
    __syncthreads();

    const float* q = Q + ((size_t)b * D_SZ + (size_t)c * 256) * H_SZ + t;
    float acc = 0.0f;
    #pragma unroll 8
    for (int i = 0; i < 256; i++)
        acc = fmaf(ws[i], q[(size_t)i * H_SZ], acc);

    g_partial[((size_t)b * NCHUNK + c) * H_SZ + t] = acc;
}

// ---------------------------------------------------------------------------
// Kernel 5: reduce partials -> output (B, 1, H). grid = B_SZ, block = 256.
// ---------------------------------------------------------------------------
__global__ void finalize_kernel(float* __restrict__ out) {
    int b = blockIdx.x;
    int h = threadIdx.x;
    float s = 0.0f;
    #pragma unroll
    for (int c = 0; c < NCHUNK; c++)
        s += g_partial[((size_t)b * NCHUNK + c) * H_SZ + h];
    out[b * H_SZ + h] = s;
}

// ---------------------------------------------------------------------------
// Launch. Inputs in metadata order:
// 0 context (B,H) | 1 question (B,D,H) | 2 hidden (1,B,H) | 3 W1 (H,H)
// 4 W2 (H,H) | 5 b2 (H) | 6 W3 (H,H) | 7 W4 (1,H) | 8 b4 (1)
// ---------------------------------------------------------------------------
extern "C" void kernel_launch(void* const* d_in, const int* in_sizes, int n_in,
                              void* d_out, int out_size) {
    const float* ctx = (const float*)d_in[0];
    const float* qn  = (const float*)d_in[1];
    const float* hid = (const float*)d_in[2];
    const float* W1  = (const float*)d_in[3];
    const float* W2  = (const float*)d_in[4];
    const float* b2  = (const float*)d_in[5];
    const float* W3  = (const float*)d_in[6];
    const float* W4  = (const float*)d_in[7];
    const float* b4  = (const float*)d_in[8];
    float* out = (float*)d_out;

    // Idempotent, capture-safe (immediate host-side attribute, not a stream op)
    cudaFuncSetAttribute(gemm_score_kernel,
                         cudaFuncAttributeMaxDynamicSharedMemorySize, SMEM_BYTES);

    bias_kernel<<<B_SZ, H_SZ>>>(ctx, hid, W2, b2, W3);
    gemm_score_kernel<<<dim3(DT, B_SZ), 256, SMEM_BYTES>>>(qn, W1, W4, b4);
    softmax_kernel<<<B_SZ, 256>>>();
    wsum_kernel<<<dim3(NCHUNK, B_SZ), 256>>>(qn);
    finalize_kernel<<<B_SZ, 256>>>(out);
}

// round 2
// speedup vs baseline: 5.2794x; 5.2794x over previous
#include <cuda_runtime.h>
#include <cuda_bf16.h>
#include <math.h>
#include <stdint.h>

// Problem constants (fixed by setup_inputs)
#define B_SZ 64
#define D_SZ 2048
#define H_SZ 256
#define NCHUNK 8           // softmax/scores chunking: D/256

// GEMM tiling
#define TILE_M 128         // d-rows per CTA
#define NDT    (D_SZ / TILE_M)   // 16 d-tiles
#define A_STR  260         // As row stride (floats): %32==4 -> conflict-free frags
#define B_STR  68          // Bs row stride (floats): %32==4 -> conflict-free frags
#define DYN_SMEM ((TILE_M * A_STR + H_SZ * B_STR) * 4)

// Scratch (allocation-free rule: __device__ globals)
__device__ float g_scores [B_SZ * D_SZ];            // scores -> softmax weights (in-place)
__device__ float g_bias   [B_SZ * H_SZ];            // c[b][h] = W2@ctx + b2 + W3@hid
__device__ float g_partial[B_SZ * 32 * H_SZ];       // weighted-sum partials (8 chunks x 4 subd)

__device__ __forceinline__ uint32_t f2tf32(float x) {
    uint32_t r;
    asm("cvt.rna.tf32.f32 %0, %1;" : "=r"(r) : "f"(x));
    return r;
}
__device__ __forceinline__ float tanh_fast(float x) {
    float y;
    asm("tanh.approx.f32 %0, %1;" : "=f"(y) : "f"(x));
    return y;
}
__device__ __forceinline__ void mma_tf32(float d[4], const uint32_t a[4], const uint32_t b[2]) {
    asm volatile(
        "mma.sync.aligned.m16n8k8.row.col.f32.tf32.tf32.f32 "
        "{%0,%1,%2,%3}, {%4,%5,%6,%7}, {%8,%9}, {%0,%1,%2,%3};"
        : "+f"(d[0]), "+f"(d[1]), "+f"(d[2]), "+f"(d[3])
        : "r"(a[0]), "r"(a[1]), "r"(a[2]), "r"(a[3]), "r"(b[0]), "r"(b[1]));
}

// ---------------------------------------------------------------------------
// Kernel 1: per-batch bias vector c[b][h] (tiny)
// ---------------------------------------------------------------------------
__global__ void bias_kernel(const float* __restrict__ ctx,
                            const float* __restrict__ hid,
                            const float* __restrict__ W2,
                            const float* __restrict__ b2,
                            const float* __restrict__ W3) {
    int b = blockIdx.x;
    int h = threadIdx.x;
    __shared__ float cs[H_SZ];
    __shared__ float hs[H_SZ];
    cs[h] = ctx[b * H_SZ + h];
    hs[h] = hid[b * H_SZ + h];
    __syncthreads();

    const float4* w2r = reinterpret_cast<const float4*>(W2 + (size_t)h * H_SZ);
    const float4* w3r = reinterpret_cast<const float4*>(W3 + (size_t)h * H_SZ);
    float acc = b2[h];
    #pragma unroll 8
    for (int k4 = 0; k4 < H_SZ / 4; k4++) {
        float4 w2v = w2r[k4];
        float4 w3v = w3r[k4];
        int k = k4 * 4;
        acc += cs[k+0]*w2v.x + cs[k+1]*w2v.y + cs[k+2]*w2v.z + cs[k+3]*w2v.w;
        acc += hs[k+0]*w3v.x + hs[k+1]*w3v.y + hs[k+2]*w3v.z + hs[k+3]*w3v.w;
    }
    g_bias[b * H_SZ + h] = acc;
}

// ---------------------------------------------------------------------------
// Kernel 2: tf32 MMA GEMM (question @ W1^T) fused with tanh(.+c)·W4 -> scores.
// CTA: 128 M x 256 N x 256 K. 8 warps: warp_n = wid%4 (64 cols), warp_m =
// wid/4 (64 rows). Warp tile 64x64 = 4 m-subtiles x 8 n-tiles of m16n8k8.
// A (question tile) in SMEM stride 260; W1 k-slices (64) in SMEM stride 68.
// Both strides are %32==4 -> fragment LDS bank-conflict-free.
// ---------------------------------------------------------------------------
__global__ void __launch_bounds__(256, 1)
gemm_score_mma(const float* __restrict__ Q,
               const float* __restrict__ W1,
               const float* __restrict__ W4,
               const float* __restrict__ b4) {
    extern __shared__ float sm[];
    float* As = sm;                       // [128][A_STR]
    float* Bs = sm + TILE_M * A_STR;      // [256][B_STR]
    __shared__ float cs[H_SZ];
    __shared__ float w4s[H_SZ];
    __shared__ float spart[TILE_M][4];    // per-row partial scores per warp_n

    const int b    = blockIdx.y;
    const int dt   = blockIdx.x;
    const int tid  = threadIdx.x;
    const int wid  = tid >> 5;
    const int lane = tid & 31;
    const int wm   = wid >> 2;            // warp_m: 0..1
    const int wn   = wid & 3;             // warp_n: 0..3
    const int gq   = lane >> 2;           // groupID 0..7
    const int tq   = lane & 3;            // threadID-in-group 0..3

    cs[tid]  = g_bias[b * H_SZ + tid];
    w4s[tid] = W4[tid];

    // Load A tile (128 x 256) -> As, tf32-rounded. Scalar stores (stride 260
    // rows are not 16B-aligned). 32 float4 gmem reads per thread, coalesced.
    {
        const float4* qg = reinterpret_cast<const float4*>(
            Q + ((size_t)b * D_SZ + (size_t)dt * TILE_M) * H_SZ);
        #pragma unroll
        for (int it = 0; it < 32; it++) {
            int idx = it * 256 + tid;     // float4 index in 128x64 grid
            int row = idx >> 6;
            int c4  = idx & 63;
            float4 v = qg[idx];
            float* dst = As + row * A_STR + c4 * 4;
            dst[0] = __uint_as_float(f2tf32(v.x));
            dst[1] = __uint_as_float(f2tf32(v.y));
            dst[2] = __uint_as_float(f2tf32(v.z));
            dst[3] = __uint_as_float(f2tf32(v.w));
        }
    }

    float acc[4][8][4];
    #pragma unroll
    for (int i = 0; i < 4; i++)
        #pragma unroll
        for (int j = 0; j < 8; j++)
            #pragma unroll
            for (int r = 0; r < 4; r++) acc[i][j][r] = 0.0f;

    for (int kb = 0; kb < 4; kb++) {
        __syncthreads();   // previous Bs consumed (also orders A stores, iter 0)
        // Load W1 k-slice: thread owns row h=tid, 64 contiguous floats.
        {
            const float4* w1r = reinterpret_cast<const float4*>(
                W1 + (size_t)tid * H_SZ + kb * 64);
            float* brow = Bs + tid * B_STR;
            #pragma unroll
            for (int q4 = 0; q4 < 16; q4++) {
                float4 v = w1r[q4];
                float4 o;
                o.x = __uint_as_float(f2tf32(v.x));
                o.y = __uint_as_float(f2tf32(v.y));
                o.z = __uint_as_float(f2tf32(v.z));
                o.w = __uint_as_float(f2tf32(v.w));
                *reinterpret_cast<float4*>(brow + q4 * 4) = o;
            }
        }
        __syncthreads();

        #pragma unroll
        for (int kk = 0; kk < 8; kk++) {
            const int kA = kb * 64 + kk * 8 + tq;  // col in As
            const int kB = kk * 8 + tq;            // col in Bs

            uint32_t afr[4][4];
            #pragma unroll
            for (int ms = 0; ms < 4; ms++) {
                const float* ap = As + (wm * 64 + ms * 16 + gq) * A_STR + kA;
                afr[ms][0] = __float_as_uint(ap[0]);
                afr[ms][1] = __float_as_uint(ap[8 * A_STR]);
                afr[ms][2] = __float_as_uint(ap[4]);
                afr[ms][3] = __float_as_uint(ap[8 * A_STR + 4]);
            }
            uint32_t bfr[8][2];
            #pragma unroll
            for (int nt = 0; nt < 8; nt++) {
                const float* bp = Bs + (wn * 64 + nt * 8 + gq) * B_STR + kB;
                bfr[nt][0] = __float_as_uint(bp[0]);
                bfr[nt][1] = __float_as_uint(bp[4]);
            }
            #pragma unroll
            for (int ms = 0; ms < 4; ms++)
                #pragma unroll
                for (int nt = 0; nt < 8; nt++)
                    mma_tf32(acc[ms][nt], afr[ms], bfr[nt]);
        }
    }

    // Fused epilogue: score[row] = sum_h tanh(v+c[h])*W4[h] + b4
    #pragma unroll
    for (int ms = 0; ms < 4; ms++) {
        const int rowA = wm * 64 + ms * 16 + gq;
        const int rowB = rowA + 8;
        float sA = 0.0f, sB = 0.0f;
        #pragma unroll
        for (int nt = 0; nt < 8; nt++) {
            const int c0 = wn * 64 + nt * 8 + 2 * tq;
            const float w0 = w4s[c0], w1 = w4s[c0 + 1];
            const float cc0 = cs[c0], cc1 = cs[c0 + 1];
            sA += tanh_fast(acc[ms][nt][0] + cc0) * w0
                + tanh_fast(acc[ms][nt][1] + cc1) * w1;
            sB += tanh_fast(acc[ms][nt][2] + cc0) * w0
                + tanh_fast(acc[ms][nt][3] + cc1) * w1;
        }
        sA += __shfl_xor_sync(0xffffffffu, sA, 1);
        sA += __shfl_xor_sync(0xffffffffu, sA, 2);
        sB += __shfl_xor_sync(0xffffffffu, sB, 1);
        sB += __shfl_xor_sync(0xffffffffu, sB, 2);
        if (tq == 0) {
            spart[rowA][wn] = sA;
            spart[rowB][wn] = sB;
        }
    }
    __syncthreads();
    if (tid < TILE_M) {
        float s = spart[tid][0] + spart[tid][1] + spart[tid][2] + spart[tid][3] + b4[0];
        g_scores[b * D_SZ + dt * TILE_M + tid] = s;
    }
}

// ---------------------------------------------------------------------------
// Kernel 3: softmax over D per batch. grid = B_SZ, block = 256.
// ---------------------------------------------------------------------------
__global__ void softmax_kernel() {
    int b   = blockIdx.x;
    int tid = threadIdx.x;
    __shared__ float red[256];

    float v[NCHUNK];
    float m = -1e30f;
    #pragma unroll
    for (int i = 0; i < NCHUNK; i++) {
        v[i] = g_scores[b * D_SZ + i * 256 + tid];
        m = fmaxf(m, v[i]);
    }
    red[tid] = m;
    __syncthreads();
    for (int s = 128; s > 0; s >>= 1) {
        if (tid < s) red[tid] = fmaxf(red[tid], red[tid + s]);
        __syncthreads();
    }
    m = red[0];
    __syncthreads();

    float ssum = 0.0f;
    #pragma unroll
    for (int i = 0; i < NCHUNK; i++) {
        v[i] = expf(v[i] - m);
        ssum += v[i];
    }
    red[tid] = ssum;
    __syncthreads();
    for (int s = 128; s > 0; s >>= 1) {
        if (tid < s) red[tid] += red[tid + s];
        __syncthreads();
    }
    float inv = 1.0f / red[0];

    #pragma unroll
    for (int i = 0; i < NCHUNK; i++)
        g_scores[b * D_SZ + i * 256 + tid] = v[i] * inv;
}

// ---------------------------------------------------------------------------
// Kernel 4: weighted partial sums, float4 per thread. grid=(8,B), block=256.
// Thread t: h4 = t&63 (float4 h-chunk), sd = t>>6 (64-row sub-block).
// ---------------------------------------------------------------------------
__global__ void __launch_bounds__(256)
wsum_kernel(const float* __restrict__ Q) {
    int b = blockIdx.y;
    int c = blockIdx.x;
    int t = threadIdx.x;
    int h4 = t & 63;
    int sd = t >> 6;
    __shared__ float ws[256];
    ws[t] = g_scores[b * D_SZ + c * 256 + t];
    __syncthreads();

    const float4* q = reinterpret_cast<const float4*>(
        Q + ((size_t)b * D_SZ + (size_t)c * 256 + (size_t)sd * 64) * H_SZ);
    const float* w = ws + sd * 64;
    float4 acc = make_float4(0.f, 0.f, 0.f, 0.f);
    #pragma unroll 8
    for (int i = 0; i < 64; i++) {
        float4 v = q[i * 64 + h4];
        float wv = w[i];
        acc.x = fmaf(wv, v.x, acc.x);
        acc.y = fmaf(wv, v.y, acc.y);
        acc.z = fmaf(wv, v.z, acc.z);
        acc.w = fmaf(wv, v.w, acc.w);
    }
    float4* dst = reinterpret_cast<float4*>(
        g_partial + (((size_t)b * NCHUNK + c) * 4 + sd) * H_SZ);
    dst[h4] = acc;
}

// ---------------------------------------------------------------------------
// Kernel 5: reduce 32 partials -> output (B,1,H). grid = B_SZ, block = 256.
// ---------------------------------------------------------------------------
__global__ void finalize_kernel(float* __restrict__ out) {
    int b = blockIdx.x;
    int h = threadIdx.x;
    float s = 0.0f;
    #pragma unroll
    for (int p = 0; p < 32; p++)
        s += g_partial[((size_t)b * 32 + p) * H_SZ + h];
    out[b * H_SZ + h] = s;
}

// ---------------------------------------------------------------------------
// Launch. Inputs: 0 context | 1 question | 2 hidden | 3 W1 | 4 W2 | 5 b2
//                 6 W3 | 7 W4 | 8 b4
// ---------------------------------------------------------------------------
extern "C" void kernel_launch(void* const* d_in, const int* in_sizes, int n_in,
                              void* d_out, int out_size) {
    const float* ctx = (const float*)d_in[0];
    const float* qn  = (const float*)d_in[1];
    const float* hid = (const float*)d_in[2];
    const float* W1  = (const float*)d_in[3];
    const float* W2  = (const float*)d_in[4];
    const float* b2  = (const float*)d_in[5];
    const float* W3  = (const float*)d_in[6];
    const float* W4  = (const float*)d_in[7];
    const float* b4  = (const float*)d_in[8];
    float* out = (float*)d_out;

    cudaFuncSetAttribute(gemm_score_mma,
                         cudaFuncAttributeMaxDynamicSharedMemorySize, DYN_SMEM);

    bias_kernel<<<B_SZ, H_SZ>>>(ctx, hid, W2, b2, W3);
    gemm_score_mma<<<dim3(NDT, B_SZ), 256, DYN_SMEM>>>(qn, W1, W4, b4);
    softmax_kernel<<<B_SZ, 256>>>();
    wsum_kernel<<<dim3(NCHUNK, B_SZ), 256>>>(qn);
    finalize_kernel<<<B_SZ, 256>>>(out);
}

// round 4
// speedup vs baseline: 8.8874x; 1.6834x over previous
#include <cuda_runtime.h>
#include <cuda_bf16.h>
#include <math.h>
#include <stdint.h>

// Problem constants
#define B_SZ 64
#define D_SZ 2048
#define H_SZ 256
#define NCHUNK 8

// GEMM tiling: CTA = 128 M x 256 N x 256 K, bf16 fully resident in smem.
#define TILE_M 128
#define NDT    (D_SZ / TILE_M)       // 16
#define KP     (H_SZ / 2)            // 128 bf16x2 pairs per row
#define ROWP   132                   // padded row stride in b32 (128 + 4)
#define A_B32  (TILE_M * ROWP)       // 16896
#define B_B32  (H_SZ * ROWP)         // 33792
#define DYN_SMEM ((A_B32 + B_B32) * 4)   // 202752 bytes

// Scratch (__device__ globals: allocation-free rule)
__device__ float    g_scores [B_SZ * D_SZ];
__device__ float    g_bias   [B_SZ * H_SZ];
__device__ float    g_partial[B_SZ * 64 * H_SZ];
__device__ uint32_t g_w1bf   [H_SZ * H_SZ / 2];   // W1 as bf16x2 pairs

// ---------------- helpers ----------------
__device__ __forceinline__ uint32_t smem_u32(const void* p) {
    uint32_t a;
    asm("{ .reg .u64 t; cvta.to.shared.u64 t, %1; cvt.u32.u64 %0, t; }" : "=r"(a) : "l"(p));
    return a;
}
__device__ __forceinline__ float tanh_fast(float x) {
    float y;
    asm("tanh.approx.f32 %0, %1;" : "=f"(y) : "f"(x));
    return y;
}
__device__ __forceinline__ uint32_t pack_bf16(float lo, float hi) {
    uint32_t r;
    asm("cvt.rn.bf16x2.f32 %0, %1, %2;" : "=r"(r) : "f"(hi), "f"(lo));
    return r;
}
__device__ __forceinline__ void cp16(uint32_t dst, const void* src) {
    asm volatile("cp.async.cg.shared.global [%0], [%1], 16;" :: "r"(dst), "l"(src));
}
__device__ __forceinline__ void mma_bf16(float* d, const uint32_t* a, const uint32_t* b) {
    asm volatile(
        "mma.sync.aligned.m16n8k16.row.col.f32.bf16.bf16.f32 "
        "{%0,%1,%2,%3}, {%4,%5,%6,%7}, {%8,%9}, {%0,%1,%2,%3};"
        : "+f"(d[0]), "+f"(d[1]), "+f"(d[2]), "+f"(d[3])
        : "r"(a[0]), "r"(a[1]), "r"(a[2]), "r"(a[3]), "r"(b[0]), "r"(b[1]));
}

// ---------------------------------------------------------------------------
// Kernel 0: convert W1 (fp32, row-major [out][k]) -> bf16x2 pairs.
// grid = 128, block = 256  (32768 pairs)
// ---------------------------------------------------------------------------
__global__ void w1cvt_kernel(const float* __restrict__ W1) {
    int i = blockIdx.x * 256 + threadIdx.x;
    float2 v = reinterpret_cast<const float2*>(W1)[i];
    g_w1bf[i] = pack_bf16(v.x, v.y);
}

// ---------------------------------------------------------------------------
// Kernel 1: bias c[b][h] = W2@ctx + b2 + W3@hid
// ---------------------------------------------------------------------------
__global__ void bias_kernel(const float* __restrict__ ctx,
                            const float* __restrict__ hid,
                            const float* __restrict__ W2,
                            const float* __restrict__ b2,
                            const float* __restrict__ W3) {
    int b = blockIdx.x;
    int h = threadIdx.x;
    __shared__ float cs[H_SZ];
    __shared__ float hs[H_SZ];
    cs[h] = ctx[b * H_SZ + h];
    hs[h] = hid[b * H_SZ + h];
    __syncthreads();

    const float4* w2r = reinterpret_cast<const float4*>(W2 + (size_t)h * H_SZ);
    const float4* w3r = reinterpret_cast<const float4*>(W3 + (size_t)h * H_SZ);
    float acc = b2[h];
    #pragma unroll 8
    for (int k4 = 0; k4 < H_SZ / 4; k4++) {
        float4 a = w2r[k4], c = w3r[k4];
        int k = k4 * 4;
        acc += cs[k]*a.x + cs[k+1]*a.y + cs[k+2]*a.z + cs[k+3]*a.w;
        acc += hs[k]*c.x + hs[k+1]*c.y + hs[k+2]*c.z + hs[k+3]*c.w;
    }
    g_bias[b * H_SZ + h] = acc;
}

// ---------------------------------------------------------------------------
// Kernel 2: bf16 mma GEMM (Q @ W1^T) fused with tanh(.+c)·W4 -> scores.
// 512 threads, 16 warps: wm = wid>>3 (2), wn = wid&7 (8). Warp tile 64x32:
// 4 m-subtiles x 4 n-subtiles of m16n8k16. A+B fully smem-resident,
// padded stride 132 b32 -> all fragment LDS bank-conflict-free (4*gq+tq).
// No barriers in the k-loop.
// ---------------------------------------------------------------------------
__global__ void __launch_bounds__(512, 1)
gemm_score_bf16(const float* __restrict__ Q,
                const float* __restrict__ W4,
                const float* __restrict__ b4) {
    extern __shared__ uint32_t sm[];
    uint32_t* As = sm;                 // [128][132] bf16x2
    uint32_t* Bs = sm + A_B32;         // [256][132] bf16x2
    __shared__ float cs[H_SZ];
    __shared__ float w4s[H_SZ];
    __shared__ float spart[TILE_M][8];

    const int b    = blockIdx.y;
    const int dt   = blockIdx.x;
    const int tid  = threadIdx.x;
    const int wid  = tid >> 5;
    const int lane = tid & 31;
    const int wm   = wid >> 3;         // 0..1
    const int wn   = wid & 7;          // 0..7
    const int gq   = lane >> 2;        // 0..7
    const int tq   = lane & 3;         // 0..3

    if (tid < H_SZ) {
        cs[tid]  = g_bias[b * H_SZ + tid];
        w4s[tid] = W4[tid];
    }

    // --- Load B (W1 bf16) via cp.async: 256 rows x 512B, 16 chunks/thread ---
    {
        const uint32_t bbase = smem_u32(Bs);
        const char* src = reinterpret_cast<const char*>(g_w1bf);
        #pragma unroll
        for (int j = 0; j < 16; j++) {
            int idx = j * 512 + tid;
            int n = idx >> 5, c = idx & 31;
            cp16(bbase + (uint32_t)(n * ROWP + c * 4) * 4, src + n * 512 + c * 16);
        }
        asm volatile("cp.async.commit_group;" ::: "memory");
    }

    // --- Load + convert A (question tile): 128 rows x 128 pairs ---
    {
        const float2* qg = reinterpret_cast<const float2*>(
            Q + ((size_t)b * D_SZ + (size_t)dt * TILE_M) * H_SZ);
        #pragma unroll
        for (int j = 0; j < 32; j++) {
            int idx = j * 512 + tid;
            int m = idx >> 7, p = idx & 127;
            float2 v = qg[m * KP + p];
            As[m * ROWP + p] = pack_bf16(v.x, v.y);
        }
    }
    asm volatile("cp.async.wait_group 0;" ::: "memory");
    __syncthreads();

    // --- Mainloop: 16 k-steps of 16, no barriers ---
    float acc[4][4][4];
    #pragma unroll
    for (int i = 0; i < 4; i++)
        #pragma unroll
        for (int j = 0; j < 4; j++)
            #pragma unroll
            for (int r = 0; r < 4; r++) acc[i][j][r] = 0.0f;

    const uint32_t* aRow[4];
    const uint32_t* bRow[4];
    #pragma unroll
    for (int ms = 0; ms < 4; ms++)
        aRow[ms] = As + (wm * 64 + ms * 16 + gq) * ROWP + tq;
    #pragma unroll
    for (int ns = 0; ns < 4; ns++)
        bRow[ns] = Bs + (wn * 32 + ns * 8 + gq) * ROWP + tq;

    #pragma unroll
    for (int k16 = 0; k16 < 16; k16++) {
        const int kb = k16 * 8;
        uint32_t a[4][4], bb[4][2];
        #pragma unroll
        for (int ms = 0; ms < 4; ms++) {
            a[ms][0] = aRow[ms][kb];
            a[ms][1] = aRow[ms][8 * ROWP + kb];
            a[ms][2] = aRow[ms][kb + 4];
            a[ms][3] = aRow[ms][8 * ROWP + kb + 4];
        }
        #pragma unroll
        for (int ns = 0; ns < 4; ns++) {
            bb[ns][0] = bRow[ns][kb];
            bb[ns][1] = bRow[ns][kb + 4];
        }
        #pragma unroll
        for (int ms = 0; ms < 4; ms++)
            #pragma unroll
            for (int ns = 0; ns < 4; ns++)
                mma_bf16(acc[ms][ns], a[ms], bb[ns]);
    }

    // --- Fused epilogue: score[row] = sum_h tanh(v+c[h])*W4[h] ---
    #pragma unroll
    for (int ms = 0; ms < 4; ms++) {
        const int r0 = wm * 64 + ms * 16 + gq;
        const int r1 = r0 + 8;
        float sA = 0.0f, sB = 0.0f;
        #pragma unroll
        for (int ns = 0; ns < 4; ns++) {
            const int n0 = wn * 32 + ns * 8 + 2 * tq;
            const float w0 = w4s[n0], w1 = w4s[n0 + 1];
            const float c0 = cs[n0],  c1 = cs[n0 + 1];
            sA += tanh_fast(acc[ms][ns][0] + c0) * w0
                + tanh_fast(acc[ms][ns][1] + c1) * w1;
            sB += tanh_fast(acc[ms][ns][2] + c0) * w0
                + tanh_fast(acc[ms][ns][3] + c1) * w1;
        }
        sA += __shfl_xor_sync(0xffffffffu, sA, 1);
        sA += __shfl_xor_sync(0xffffffffu, sA, 2);
        sB += __shfl_xor_sync(0xffffffffu, sB, 1);
        sB += __shfl_xor_sync(0xffffffffu, sB, 2);
        if (tq == 0) {
            spart[r0][wn] = sA;
            spart[r1][wn] = sB;
        }
    }
    __syncthreads();
    if (tid < TILE_M) {
        float s = b4[0];
        #pragma unroll
        for (int w = 0; w < 8; w++) s += spart[tid][w];
        g_scores[b * D_SZ + dt * TILE_M + tid] = s;
    }
}

// ---------------------------------------------------------------------------
// Kernel 3: softmax over D per batch. grid = B_SZ, block = 256.
// ---------------------------------------------------------------------------
__global__ void softmax_kernel() {
    int b = blockIdx.x;
    int tid = threadIdx.x;
    __shared__ float red[256];

    float v[NCHUNK];
    float m = -1e30f;
    #pragma unroll
    for (int i = 0; i < NCHUNK; i++) {
        v[i] = g_scores[b * D_SZ + i * 256 + tid];
        m = fmaxf(m, v[i]);
    }
    red[tid] = m;
    __syncthreads();
    for (int s = 128; s > 0; s >>= 1) {
        if (tid < s) red[tid] = fmaxf(red[tid], red[tid + s]);
        __syncthreads();
    }
    m = red[0];
    __syncthreads();

    float ssum = 0.0f;
    #pragma unroll
    for (int i = 0; i < NCHUNK; i++) { v[i] = expf(v[i] - m); ssum += v[i]; }
    red[tid] = ssum;
    __syncthreads();
    for (int s = 128; s > 0; s >>= 1) {
        if (tid < s) red[tid] += red[tid + s];
        __syncthreads();
    }
    float inv = 1.0f / red[0];

    #pragma unroll
    for (int i = 0; i < NCHUNK; i++)
        g_scores[b * D_SZ + i * 256 + tid] = v[i] * inv;
}

// ---------------------------------------------------------------------------
// Kernel 4: weighted partial sums, 128-row chunks. grid=(16,B), block=256.
// ---------------------------------------------------------------------------
__global__ void __launch_bounds__(256)
wsum_kernel(const float* __restrict__ Q) {
    int b = blockIdx.y;
    int c = blockIdx.x;       // 0..15
    int t = threadIdx.x;
    int h4 = t & 63;
    int sd = t >> 6;          // 0..3
    __shared__ float ws[128];
    if (t < 128) ws[t] = g_scores[b * D_SZ + c * 128 + t];
    __syncthreads();

    const float4* q = reinterpret_cast<const float4*>(
        Q + ((size_t)b * D_SZ + (size_t)c * 128 + (size_t)sd * 32) * H_SZ);
    const float* w = ws + sd * 32;
    float4 acc = make_float4(0.f, 0.f, 0.f, 0.f);
    #pragma unroll 8
    for (int i = 0; i < 32; i++) {
        float4 v = q[i * 64 + h4];
        float wv = w[i];
        acc.x = fmaf(wv, v.x, acc.x);
        acc.y = fmaf(wv, v.y, acc.y);
        acc.z = fmaf(wv, v.z, acc.z);
        acc.w = fmaf(wv, v.w, acc.w);
    }
    float4* dst = reinterpret_cast<float4*>(
        g_partial + ((size_t)b * 64 + (size_t)c * 4 + sd) * H_SZ);
    dst[h4] = acc;
}

// ---------------------------------------------------------------------------
// Kernel 5: reduce 64 partials -> out (B,1,H). grid = B_SZ, block = 256.
// ---------------------------------------------------------------------------
__global__ void finalize_kernel(float* __restrict__ out) {
    int b = blockIdx.x;
    int h = threadIdx.x;
    float s = 0.0f;
    #pragma unroll
    for (int p = 0; p < 64; p++)
        s += g_partial[((size_t)b * 64 + p) * H_SZ + h];
    out[b * H_SZ + h] = s;
}

// ---------------------------------------------------------------------------
// Launch. Inputs: 0 context | 1 question | 2 hidden | 3 W1 | 4 W2 | 5 b2
//                 6 W3 | 7 W4 | 8 b4
// ---------------------------------------------------------------------------
extern "C" void kernel_launch(void* const* d_in, const int* in_sizes, int n_in,
                              void* d_out, int out_size) {
    const float* ctx = (const float*)d_in[0];
    const float* qn  = (const float*)d_in[1];
    const float* hid = (const float*)d_in[2];
    const float* W1  = (const float*)d_in[3];
    const float* W2  = (const float*)d_in[4];
    const float* b2  = (const float*)d_in[5];
    const float* W3  = (const float*)d_in[6];
    const float* W4  = (const float*)d_in[7];
    const float* b4  = (const float*)d_in[8];
    float* out = (float*)d_out;

    cudaFuncSetAttribute(gemm_score_bf16,
                         cudaFuncAttributeMaxDynamicSharedMemorySize, DYN_SMEM);

    w1cvt_kernel<<<128, 256>>>(W1);
    bias_kernel<<<B_SZ, H_SZ>>>(ctx, hid, W2, b2, W3);
    gemm_score_bf16<<<dim3(NDT, B_SZ), 512, DYN_SMEM>>>(qn, W4, b4);
    softmax_kernel<<<B_SZ, 256>>>();
    wsum_kernel<<<dim3(16, B_SZ), 256>>>(qn);
    finalize_kernel<<<B_SZ, 256>>>(out);
}